// round 1
// baseline (speedup 1.0000x reference)
#include <cuda_runtime.h>
#include <cuda_bf16.h>

// ---------------------------------------------------------------------------
// Problem constants (from reference setup_inputs)
// ---------------------------------------------------------------------------
#define MAX_NODES 100000
#define MAX_EDGES 1600000
#define D 128

// Scratch buffers (device globals; no allocations allowed)
__device__ float g_hW  [(size_t)MAX_NODES * 128];   // 51.2 MB
__device__ float g_agg [(size_t)MAX_NODES * 128];   // 51.2 MB
__device__ float g_xcat[(size_t)MAX_NODES * 256];   // 102.4 MB
__device__ float g_gx  [(size_t)MAX_NODES * 384];   // 153.6 MB
__device__ float g_gh  [(size_t)MAX_NODES * 384];   // 153.6 MB

// ---------------------------------------------------------------------------
// Tiled SGEMM: C[M,N] = A[M,K] @ B'  where B'[k][j] = TRANSB ? B[j*ldb+k]
//                                                           : B[k*ldb+j]
// Optional row-gather on A (GATHER: row index = gidx[row]).
// BM=128, BN=128, BK=8, 256 threads, 8x8 per-thread tile.
// Requires: N % 128 == 0, K % 8 == 0. M arbitrary (predicated).
// ---------------------------------------------------------------------------
#define BM 128
#define BN 128
#define BK 8
#define TM 8
#define TN 8

template<bool TRANSB, bool GATHER>
__global__ __launch_bounds__(256)
void sgemm_kernel(int M, int N, int K,
                  const float* __restrict__ A, int lda,
                  const float* __restrict__ B, int ldb,
                  float* __restrict__ C, int ldc,
                  const int* __restrict__ gidx)
{
    __shared__ float As[BK][BM];
    __shared__ float Bs[BK][BN];

    const int tid = threadIdx.x;
    const int rowBase = blockIdx.y * BM;
    const int colBase = blockIdx.x * BN;

    const int tRow = (tid / 16) * TM;
    const int tCol = (tid % 16) * TN;

    float acc[TM][TN];
#pragma unroll
    for (int i = 0; i < TM; i++)
#pragma unroll
        for (int j = 0; j < TN; j++) acc[i][j] = 0.f;

    // A tile load mapping: 128 rows x 8 k -> 256 float4 (1 per thread)
    const int aRow = tid >> 1;
    const int aK   = (tid & 1) * 4;
    const int aGlobalRow = rowBase + aRow;
    const bool aValid = aGlobalRow < M;
    long aRowIdx = 0;
    if (aValid) aRowIdx = GATHER ? (long)gidx[aGlobalRow] : (long)aGlobalRow;

    for (int k0 = 0; k0 < K; k0 += BK) {
        // ---- load A tile (transposed into As[k][row]) ----
        float4 av = make_float4(0.f, 0.f, 0.f, 0.f);
        if (aValid)
            av = *(const float4*)(A + aRowIdx * lda + k0 + aK);
        As[aK + 0][aRow] = av.x;
        As[aK + 1][aRow] = av.y;
        As[aK + 2][aRow] = av.z;
        As[aK + 3][aRow] = av.w;

        // ---- load B tile ----
        if (!TRANSB) {
            const int bk = tid >> 5;            // 0..7
            const int bc = (tid & 31) * 4;      // 0..124
            float4 bv = *(const float4*)(B + (long)(k0 + bk) * ldb + colBase + bc);
            *(float4*)&Bs[bk][bc] = bv;
        } else {
            const int bj = tid >> 1;            // 0..127
            const int bk = (tid & 1) * 4;       // 0 or 4
            float4 bv = *(const float4*)(B + (long)(colBase + bj) * ldb + k0 + bk);
            Bs[bk + 0][bj] = bv.x;
            Bs[bk + 1][bj] = bv.y;
            Bs[bk + 2][bj] = bv.z;
            Bs[bk + 3][bj] = bv.w;
        }
        __syncthreads();

#pragma unroll
        for (int kk = 0; kk < BK; kk++) {
            float ra[TM], rb[TN];
#pragma unroll
            for (int i = 0; i < TM; i++) ra[i] = As[kk][tRow + i];
#pragma unroll
            for (int j = 0; j < TN; j++) rb[j] = Bs[kk][tCol + j];
#pragma unroll
            for (int i = 0; i < TM; i++)
#pragma unroll
                for (int j = 0; j < TN; j++)
                    acc[i][j] += ra[i] * rb[j];
        }
        __syncthreads();
    }

    // ---- store ----
#pragma unroll
    for (int i = 0; i < TM; i++) {
        const int r = rowBase + tRow + i;
        if (r < M) {
#pragma unroll
            for (int j = 0; j < TN; j += 4) {
                float4 v = make_float4(acc[i][j], acc[i][j+1], acc[i][j+2], acc[i][j+3]);
                *(float4*)(C + (long)r * ldc + colBase + tCol + j) = v;
            }
        }
    }
}

// ---------------------------------------------------------------------------
// Zero a float buffer (float4 granularity)
// ---------------------------------------------------------------------------
__global__ void zero_kernel(float4* __restrict__ p, long n4)
{
    long i = (long)blockIdx.x * blockDim.x + threadIdx.x;
    if (i < n4) p[i] = make_float4(0.f, 0.f, 0.f, 0.f);
}

// ---------------------------------------------------------------------------
// Edge scatter: agg[dst] += hW[src].  One edge per warp; each lane handles
// 4 floats via red.global.add.v4.f32 (sm_90+ vector reduction).
// ---------------------------------------------------------------------------
__global__ __launch_bounds__(256)
void scatter_kernel(const float* __restrict__ hW,
                    const int* __restrict__ esrc,
                    const int* __restrict__ edst,
                    float* __restrict__ agg, int E)
{
    const int warpId = (int)(((long)blockIdx.x * blockDim.x + threadIdx.x) >> 5);
    const int lane = threadIdx.x & 31;
    if (warpId >= E) return;
    const int s = esrc[warpId];
    const int d = edst[warpId];
    float4 v = *(const float4*)(hW + (long)s * 128 + lane * 4);
    float* dst = agg + (long)d * 128 + lane * 4;
    asm volatile("red.global.add.v4.f32 [%0], {%1, %2, %3, %4};"
                 :: "l"(dst), "f"(v.x), "f"(v.y), "f"(v.z), "f"(v.w)
                 : "memory");
}

// ---------------------------------------------------------------------------
// Build xcat[n] = [agg[n] * out_norm[n], e_r_bias[n]]   (N x 256)
// ---------------------------------------------------------------------------
__global__ void build_xcat_kernel(const float* __restrict__ agg,
                                  const float* __restrict__ out_norm,
                                  const float* __restrict__ erb,
                                  float* __restrict__ xcat, int Nn)
{
    long i = (long)blockIdx.x * blockDim.x + threadIdx.x;
    long total = (long)Nn * 128;
    if (i >= total) return;
    int n = (int)(i >> 7);
    int j = (int)(i & 127);
    float s = out_norm[n];
    xcat[(long)n * 256 + j]       = agg[i] * s;
    xcat[(long)n * 256 + 128 + j] = erb[i];
}

// ---------------------------------------------------------------------------
// GRU elementwise + relu + row L2-normalize. One block (128 thr) per node.
// Gates stacked [r, z, n] (torch GRUCell semantics).
// ---------------------------------------------------------------------------
__global__ __launch_bounds__(128)
void gru_kernel(const float* __restrict__ gx, const float* __restrict__ gh,
                const float* __restrict__ bih, const float* __restrict__ bhh,
                const float* __restrict__ erb, float* __restrict__ out, int Nn)
{
    const int n = blockIdx.x;
    const int j = threadIdx.x;
    if (n >= Nn) return;
    const float* gxr = gx + (long)n * 384;
    const float* ghr = gh + (long)n * 384;

    float xr = gxr[j]       + bih[j];
    float xz = gxr[128 + j] + bih[128 + j];
    float xn = gxr[256 + j] + bih[256 + j];
    float hr = ghr[j]       + bhh[j];
    float hz = ghr[128 + j] + bhh[128 + j];
    float hn = ghr[256 + j] + bhh[256 + j];

    float r  = 1.f / (1.f + expf(-(xr + hr)));
    float z  = 1.f / (1.f + expf(-(xz + hz)));
    float nn = tanhf(xn + r * hn);
    float h  = erb[(long)n * 128 + j];
    float o  = (1.f - z) * nn + z * h;
    o = fmaxf(o, 0.f);

    // row L2 norm across 128 threads
    float ss = o * o;
#pragma unroll
    for (int off = 16; off; off >>= 1)
        ss += __shfl_xor_sync(0xffffffffu, ss, off);
    __shared__ float ws[4];
    if ((j & 31) == 0) ws[j >> 5] = ss;
    __syncthreads();
    float total = ws[0] + ws[1] + ws[2] + ws[3];
    float norm = fmaxf(sqrtf(total), 1e-12f);
    out[(long)n * 128 + j] = o / norm;
}

// ---------------------------------------------------------------------------
// kernel_launch
// Input order (metadata): 0 ent_embs, 1 rel_embs, 2 e_r_bias, 3 out_norm,
// 4 weight_neighbor, 5 gru_w_ih, 6 gru_w_hh, 7 gru_b_ih, 8 gru_b_hh,
// 9 node_id(i32), 10 edge_src(i32), 11 edge_dst(i32), 12 g_idx
// ---------------------------------------------------------------------------
extern "C" void kernel_launch(void* const* d_in, const int* in_sizes, int n_in,
                              void* d_out, int out_size)
{
    const float* ent_embs = (const float*)d_in[0];
    const float* e_r_bias = (const float*)d_in[2];
    const float* out_norm = (const float*)d_in[3];
    const float* w_nb     = (const float*)d_in[4];
    const float* w_ih     = (const float*)d_in[5];
    const float* w_hh     = (const float*)d_in[6];
    const float* b_ih     = (const float*)d_in[7];
    const float* b_hh     = (const float*)d_in[8];
    const int*   node_id  = (const int*)d_in[9];
    const int*   edge_src = (const int*)d_in[10];
    const int*   edge_dst = (const int*)d_in[11];

    const int Nn = in_sizes[3];        // out_norm is [N,1]
    const int E  = in_sizes[10];       // edge_src

    float* hW;   cudaGetSymbolAddress((void**)&hW,   g_hW);
    float* agg;  cudaGetSymbolAddress((void**)&agg,  g_agg);
    float* xcat; cudaGetSymbolAddress((void**)&xcat, g_xcat);
    float* gx;   cudaGetSymbolAddress((void**)&gx,   g_gx);
    float* gh;   cudaGetSymbolAddress((void**)&gh,   g_gh);

    float* out = (float*)d_out;

    const int Mblocks = (Nn + BM - 1) / BM;

    // 1) hW = ent_embs[node_id] @ W   (A gathered, B non-transposed [K x N])
    {
        dim3 grid(128 / BN, Mblocks);
        sgemm_kernel<false, true><<<grid, 256>>>(Nn, 128, 128,
                                                 ent_embs, 128,
                                                 w_nb, 128,
                                                 hW, 128, node_id);
    }

    // 2) zero agg
    {
        long n4 = (long)Nn * 128 / 4;
        int blocks = (int)((n4 + 255) / 256);
        zero_kernel<<<blocks, 256>>>((float4*)agg, n4);
    }

    // 3) scatter: agg[dst] += hW[src]
    {
        long threads = (long)E * 32;
        int blocks = (int)((threads + 255) / 256);
        scatter_kernel<<<blocks, 256>>>(hW, edge_src, edge_dst, agg, E);
    }

    // 4) xcat = [agg * out_norm, e_r_bias]
    {
        long total = (long)Nn * 128;
        int blocks = (int)((total + 255) / 256);
        build_xcat_kernel<<<blocks, 256>>>(agg, out_norm, e_r_bias, xcat, Nn);
    }

    // 5) gx = xcat @ w_ih^T   (M x 384, K=256; B row-major [384,256] -> TRANSB)
    {
        dim3 grid(384 / BN, Mblocks);
        sgemm_kernel<true, false><<<grid, 256>>>(Nn, 384, 256,
                                                 xcat, 256,
                                                 w_ih, 256,
                                                 gx, 384, nullptr);
    }

    // 6) gh = e_r_bias @ w_hh^T  (M x 384, K=128)
    {
        dim3 grid(384 / BN, Mblocks);
        sgemm_kernel<true, false><<<grid, 256>>>(Nn, 384, 128,
                                                 e_r_bias, 128,
                                                 w_hh, 128,
                                                 gh, 384, nullptr);
    }

    // 7) GRU + relu + normalize -> out
    {
        gru_kernel<<<Nn, 128>>>(gx, gh, b_ih, b_hh, e_r_bias, out, Nn);
    }

    (void)n_in; (void)out_size; (void)in_sizes;
}

// round 2
// speedup vs baseline: 1.6206x; 1.6206x over previous
#include <cuda_runtime.h>
#include <cuda_bf16.h>

// ---------------------------------------------------------------------------
// Problem constants
// ---------------------------------------------------------------------------
#define MAX_NODES 100000
#define MAX_EDGES 1600000

// Scratch (device globals; allocations forbidden)
__device__ float g_hW  [(size_t)MAX_NODES * 128];   // 51.2 MB
__device__ float g_agg [(size_t)MAX_NODES * 128];   // 51.2 MB
__device__ float g_gx  [(size_t)MAX_NODES * 384];   // 153.6 MB
__device__ float g_gh  [(size_t)MAX_NODES * 384];   // 153.6 MB

// ---------------------------------------------------------------------------
// TF32 tensor-core GEMM.
//   C[M,N] = Aeff[M,K] @ Beff[K,N]
//   Beff[k][n] = BTRANS ? B[n*ldb + k] : B[k*ldb + n]
//   AMODE 0: Aeff = A (lda)
//   AMODE 1: Aeff row r = A[gidx[r]] (lda)
//   AMODE 2: Aeff row r = [A[r]*rowscale[r] (128) | A2[r] (128)], K must be 256
// Block 256 thr (8 warps), tile 128x64, BK=32. Warp tile 32x32 (2x4 of m16n8k8).
// ---------------------------------------------------------------------------
#define BM2 128
#define BN2 64
#define BK2 32

__device__ __forceinline__ unsigned f2tf32(float x) {
    unsigned r;
    asm("cvt.rna.tf32.f32 %0, %1;" : "=r"(r) : "f"(x));
    return r;
}
__device__ __forceinline__ float tf32f(float x) { return __uint_as_float(f2tf32(x)); }

template<int AMODE, bool BTRANS>
__global__ __launch_bounds__(256)
void tf32_gemm(int M, int N, int K,
               const float* __restrict__ A, int lda,
               const float* __restrict__ A2,
               const float* __restrict__ rowscale,
               const int* __restrict__ gidx,
               const float* __restrict__ B, int ldb,
               float* __restrict__ C, int ldc)
{
    __shared__ float As[BM2][BK2 + 4];
    __shared__ float Bs[BN2][BK2 + 4];

    const int tid  = threadIdx.x;
    const int lane = tid & 31;
    const int warp = tid >> 5;
    const int warpM = warp & 3;   // 4 warps along M (4*32 = 128)
    const int warpN = warp >> 2;  // 2 warps along N (2*32 = 64)
    const int qr = lane >> 2;     // 0..7
    const int qc = lane & 3;      // 0..3

    const int rowBase = blockIdx.y * BM2;
    const int colBase = blockIdx.x * BN2;

    float c[2][4][4];
#pragma unroll
    for (int mi = 0; mi < 2; mi++)
#pragma unroll
        for (int ni = 0; ni < 4; ni++)
#pragma unroll
            for (int t = 0; t < 4; t++) c[mi][ni][t] = 0.f;

    // A global->smem mapping: 128 rows x 8 float4-slots = 1024 slots, 4/thread
    const int a_kq   = tid & 7;   // float4 index within k (0..7)
    const int a_row0 = tid >> 3;  // 0..31; rows a_row0 + i*32

    for (int k0 = 0; k0 < K; k0 += BK2) {
        // ---- A tile ----
#pragma unroll
        for (int i = 0; i < 4; i++) {
            const int r = a_row0 + i * 32;
            const int grow = rowBase + r;
            float4 v = make_float4(0.f, 0.f, 0.f, 0.f);
            if (grow < M) {
                if (AMODE == 0) {
                    v = *(const float4*)(A + (long)grow * lda + k0 + a_kq * 4);
                } else if (AMODE == 1) {
                    v = *(const float4*)(A + (long)gidx[grow] * lda + k0 + a_kq * 4);
                } else {
                    const int kg = k0 + a_kq * 4;
                    if (kg < 128) {
                        v = *(const float4*)(A + (long)grow * 128 + kg);
                        const float s = rowscale[grow];
                        v.x *= s; v.y *= s; v.z *= s; v.w *= s;
                    } else {
                        v = *(const float4*)(A2 + (long)grow * 128 + (kg - 128));
                    }
                }
            }
            float4 t;
            t.x = tf32f(v.x); t.y = tf32f(v.y); t.z = tf32f(v.z); t.w = tf32f(v.w);
            *(float4*)&As[r][a_kq * 4] = t;
        }
        // ---- B tile ----
        if (BTRANS) {
            // B row-major [N,K]; Bs[n][k] is a straight vector copy
#pragma unroll
            for (int i = 0; i < 2; i++) {
                const int slot = tid + i * 256;           // 0..511
                const int n  = slot >> 3;                 // 0..63
                const int kq = slot & 7;                  // 0..7
                float4 v = *(const float4*)(B + (long)(colBase + n) * ldb + k0 + kq * 4);
                float4 t;
                t.x = tf32f(v.x); t.y = tf32f(v.y); t.z = tf32f(v.z); t.w = tf32f(v.w);
                *(float4*)&Bs[n][kq * 4] = t;
            }
        } else {
            // B k-major [K,N]; transpose into Bs[n][k]
#pragma unroll
            for (int i = 0; i < 8; i++) {
                const int slot = tid + i * 256;           // 0..2047
                const int k = slot >> 6;                  // 0..31
                const int n = slot & 63;                  // 0..63
                Bs[n][k] = tf32f(B[(long)(k0 + k) * ldb + colBase + n]);
            }
        }
        __syncthreads();

        // ---- compute: 4 k-steps of 8 HMMA each ----
#pragma unroll
        for (int kt = 0; kt < BK2; kt += 8) {
            unsigned a[2][4], b[4][2];
#pragma unroll
            for (int mi = 0; mi < 2; mi++) {
                const int rb = warpM * 32 + mi * 16;
                a[mi][0] = __float_as_uint(As[rb + qr    ][kt + qc    ]);
                a[mi][1] = __float_as_uint(As[rb + qr + 8][kt + qc    ]);
                a[mi][2] = __float_as_uint(As[rb + qr    ][kt + qc + 4]);
                a[mi][3] = __float_as_uint(As[rb + qr + 8][kt + qc + 4]);
            }
#pragma unroll
            for (int ni = 0; ni < 4; ni++) {
                const int nb = warpN * 32 + ni * 8;
                b[ni][0] = __float_as_uint(Bs[nb + qr][kt + qc    ]);
                b[ni][1] = __float_as_uint(Bs[nb + qr][kt + qc + 4]);
            }
#pragma unroll
            for (int mi = 0; mi < 2; mi++)
#pragma unroll
                for (int ni = 0; ni < 4; ni++)
                    asm volatile(
                        "mma.sync.aligned.m16n8k8.row.col.f32.tf32.tf32.f32 "
                        "{%0,%1,%2,%3}, {%4,%5,%6,%7}, {%8,%9}, {%0,%1,%2,%3};\n"
                        : "+f"(c[mi][ni][0]), "+f"(c[mi][ni][1]),
                          "+f"(c[mi][ni][2]), "+f"(c[mi][ni][3])
                        : "r"(a[mi][0]), "r"(a[mi][1]), "r"(a[mi][2]), "r"(a[mi][3]),
                          "r"(b[ni][0]), "r"(b[ni][1]));
        }
        __syncthreads();
    }

    // ---- epilogue ----
#pragma unroll
    for (int mi = 0; mi < 2; mi++) {
        const int row0 = rowBase + warpM * 32 + mi * 16 + qr;
#pragma unroll
        for (int ni = 0; ni < 4; ni++) {
            const int col = colBase + warpN * 32 + ni * 8 + 2 * qc;
            if (row0 < M)
                *(float2*)(C + (long)row0 * ldc + col) =
                    make_float2(c[mi][ni][0], c[mi][ni][1]);
            if (row0 + 8 < M)
                *(float2*)(C + (long)(row0 + 8) * ldc + col) =
                    make_float2(c[mi][ni][2], c[mi][ni][3]);
        }
    }
}

// ---------------------------------------------------------------------------
// Zero a float buffer
// ---------------------------------------------------------------------------
__global__ void zero_kernel(float4* __restrict__ p, long n4)
{
    long i = (long)blockIdx.x * blockDim.x + threadIdx.x;
    if (i < n4) p[i] = make_float4(0.f, 0.f, 0.f, 0.f);
}

// ---------------------------------------------------------------------------
// Edge scatter: agg[dst] += hW[src]. 1 edge/warp, red.global.add.v4.f32/lane.
// ---------------------------------------------------------------------------
__global__ __launch_bounds__(256)
void scatter_kernel(const float* __restrict__ hW,
                    const int* __restrict__ esrc,
                    const int* __restrict__ edst,
                    float* __restrict__ agg, int E)
{
    const int warpId = (int)(((long)blockIdx.x * blockDim.x + threadIdx.x) >> 5);
    const int lane = threadIdx.x & 31;
    if (warpId >= E) return;
    const int s = esrc[warpId];
    const int d = edst[warpId];
    float4 v = *(const float4*)(hW + (long)s * 128 + lane * 4);
    float* dst = agg + (long)d * 128 + lane * 4;
    asm volatile("red.global.add.v4.f32 [%0], {%1, %2, %3, %4};"
                 :: "l"(dst), "f"(v.x), "f"(v.y), "f"(v.z), "f"(v.w)
                 : "memory");
}

// ---------------------------------------------------------------------------
// GRU elementwise + relu + row L2-normalize. One 128-thr block per node.
// ---------------------------------------------------------------------------
__global__ __launch_bounds__(128)
void gru_kernel(const float* __restrict__ gx, const float* __restrict__ gh,
                const float* __restrict__ bih, const float* __restrict__ bhh,
                const float* __restrict__ erb, float* __restrict__ out, int Nn)
{
    const int n = blockIdx.x;
    const int j = threadIdx.x;
    if (n >= Nn) return;
    const float* gxr = gx + (long)n * 384;
    const float* ghr = gh + (long)n * 384;

    float xr = gxr[j]       + bih[j];
    float xz = gxr[128 + j] + bih[128 + j];
    float xn = gxr[256 + j] + bih[256 + j];
    float hr = ghr[j]       + bhh[j];
    float hz = ghr[128 + j] + bhh[128 + j];
    float hn = ghr[256 + j] + bhh[256 + j];

    float r  = 1.f / (1.f + expf(-(xr + hr)));
    float z  = 1.f / (1.f + expf(-(xz + hz)));
    float nn = tanhf(xn + r * hn);
    float h  = erb[(long)n * 128 + j];
    float o  = (1.f - z) * nn + z * h;
    o = fmaxf(o, 0.f);

    float ss = o * o;
#pragma unroll
    for (int off = 16; off; off >>= 1)
        ss += __shfl_xor_sync(0xffffffffu, ss, off);
    __shared__ float ws[4];
    if ((j & 31) == 0) ws[j >> 5] = ss;
    __syncthreads();
    float total = ws[0] + ws[1] + ws[2] + ws[3];
    float norm = fmaxf(sqrtf(total), 1e-12f);
    out[(long)n * 128 + j] = o / norm;
}

// ---------------------------------------------------------------------------
// kernel_launch
// Inputs: 0 ent_embs, 1 rel_embs, 2 e_r_bias, 3 out_norm, 4 weight_neighbor,
// 5 gru_w_ih, 6 gru_w_hh, 7 gru_b_ih, 8 gru_b_hh, 9 node_id(i32),
// 10 edge_src(i32), 11 edge_dst(i32), 12 g_idx
// ---------------------------------------------------------------------------
extern "C" void kernel_launch(void* const* d_in, const int* in_sizes, int n_in,
                              void* d_out, int out_size)
{
    const float* ent_embs = (const float*)d_in[0];
    const float* e_r_bias = (const float*)d_in[2];
    const float* out_norm = (const float*)d_in[3];
    const float* w_nb     = (const float*)d_in[4];
    const float* w_ih     = (const float*)d_in[5];
    const float* w_hh     = (const float*)d_in[6];
    const float* b_ih     = (const float*)d_in[7];
    const float* b_hh     = (const float*)d_in[8];
    const int*   node_id  = (const int*)d_in[9];
    const int*   edge_src = (const int*)d_in[10];
    const int*   edge_dst = (const int*)d_in[11];

    const int Nn = in_sizes[3];
    const int E  = in_sizes[10];

    float* hW;  cudaGetSymbolAddress((void**)&hW,  g_hW);
    float* agg; cudaGetSymbolAddress((void**)&agg, g_agg);
    float* gx;  cudaGetSymbolAddress((void**)&gx,  g_gx);
    float* gh;  cudaGetSymbolAddress((void**)&gh,  g_gh);

    float* out = (float*)d_out;
    const int Mb = (Nn + BM2 - 1) / BM2;

    // 1) hW = ent_embs[node_id] @ W   (B k-major)
    {
        dim3 grid(128 / BN2, Mb);
        tf32_gemm<1, false><<<grid, 256>>>(Nn, 128, 128,
                                           ent_embs, 128, nullptr, nullptr, node_id,
                                           w_nb, 128, hW, 128);
    }

    // 2) zero agg
    {
        long n4 = (long)Nn * 128 / 4;
        zero_kernel<<<(int)((n4 + 255) / 256), 256>>>((float4*)agg, n4);
    }

    // 3) scatter: agg[dst] += hW[src]
    {
        long threads = (long)E * 32;
        scatter_kernel<<<(int)((threads + 255) / 256), 256>>>(hW, edge_src, edge_dst, agg, E);
    }

    // 4) gx = [agg*out_norm | e_r_bias] @ w_ih^T   (fused concat, B row-major [384,256])
    {
        dim3 grid(384 / BN2, Mb);
        tf32_gemm<2, true><<<grid, 256>>>(Nn, 384, 256,
                                          agg, 128, e_r_bias, out_norm, nullptr,
                                          w_ih, 256, gx, 384);
    }

    // 5) gh = e_r_bias @ w_hh^T
    {
        dim3 grid(384 / BN2, Mb);
        tf32_gemm<0, true><<<grid, 256>>>(Nn, 384, 128,
                                          e_r_bias, 128, nullptr, nullptr, nullptr,
                                          w_hh, 128, gh, 384);
    }

    // 6) GRU + relu + normalize
    gru_kernel<<<Nn, 128>>>(gx, gh, b_ih, b_hh, e_r_bias, out, Nn);

    (void)n_in; (void)out_size;
}

// round 3
// speedup vs baseline: 1.9454x; 1.2004x over previous
#include <cuda_runtime.h>
#include <cuda_bf16.h>

// ---------------------------------------------------------------------------
// Problem constants
// ---------------------------------------------------------------------------
#define MAX_NODES 100000
#define MAX_EDGES 1600000

// Scratch (device globals; allocations forbidden)
__device__ float g_hW  [(size_t)MAX_NODES * 128];   // 51.2 MB
__device__ float g_agg [(size_t)MAX_NODES * 128];   // 51.2 MB
__device__ float g_gx  [(size_t)MAX_NODES * 384];   // 153.6 MB
__device__ float g_gh  [(size_t)MAX_NODES * 384];   // 153.6 MB

__device__ __forceinline__ unsigned f2tf32(float x) {
    unsigned r;
    asm("cvt.rna.tf32.f32 %0, %1;" : "=r"(r) : "f"(x));
    return r;
}
__device__ __forceinline__ float tf32f(float x) { return __uint_as_float(f2tf32(x)); }

// ---------------------------------------------------------------------------
// TF32 tensor-core GEMM v2.
//   C[M,N] = Aeff[M,K] @ Beff[K,N]
//   Beff[k][n] = BTRANS ? B[n*ldb + boff + k] : B[k*ldb + n]
//   AMODE 0: Aeff = A (lda)
//   AMODE 1: Aeff row r = A[gidx[r]] (lda)
//   AMODE 2: Aeff row r = [A[r]*rowscale[r] (128) | A2[r] (128)], K == 256
// Block: 256 thr (8 warps, 2M x 4N), tile 128x128, warp tile 64x32, BK=16.
// Double-buffered smem, register-staged global prefetch.
// Requires N % 128 == 0, K % 16 == 0.
// ---------------------------------------------------------------------------
#define GBM 128
#define GBN 128
#define GBK 16
#define SPAD 20   // smem row pitch (floats); (20*r + c) % 32 distinct over frag

template<int AMODE, bool BTRANS>
__global__ __launch_bounds__(256, 2)
void tf32_gemm2(int M, int N, int K,
                const float* __restrict__ A, int lda,
                const float* __restrict__ A2,
                const float* __restrict__ rowscale,
                const int* __restrict__ gidx,
                const float* __restrict__ B, int ldb, int boff,
                float* __restrict__ C, int ldc)
{
    __shared__ float As[2][GBM][SPAD];
    __shared__ float Bs[2][GBN][SPAD];

    const int tid  = threadIdx.x;
    const int lane = tid & 31;
    const int warp = tid >> 5;
    const int warpM = warp & 1;    // 2 warps along M (2*64 = 128)
    const int warpN = warp >> 1;   // 4 warps along N (4*32 = 128)
    const int qr = lane >> 2;      // 0..7
    const int qc = lane & 3;       // 0..3

    const int rowBase = blockIdx.y * GBM;
    const int colBase = blockIdx.x * GBN;

    // ---- loader mapping: 512 float4 slots per tile, 2 per thread ----
    const int lr0 = tid >> 2;          // rows lr0 and lr0+64
    const int lr1 = lr0 + 64;
    const int lkq = (tid & 3) * 4;     // k offset within BK (0,4,8,12)

    const int g0 = rowBase + lr0;
    const int g1 = rowBase + lr1;
    const bool v0 = g0 < M;
    const bool v1 = g1 < M;

    long ar0 = 0, ar1 = 0;
    float s0 = 0.f, s1 = 0.f;
    if (AMODE == 1) {
        ar0 = v0 ? (long)gidx[g0] : 0;
        ar1 = v1 ? (long)gidx[g1] : 0;
    } else {
        ar0 = g0; ar1 = g1;
    }
    if (AMODE == 2) {
        s0 = v0 ? rowscale[g0] : 0.f;
        s1 = v1 ? rowscale[g1] : 0.f;
    }

    float acc[4][4][4];
#pragma unroll
    for (int mi = 0; mi < 4; mi++)
#pragma unroll
        for (int ni = 0; ni < 4; ni++)
#pragma unroll
            for (int t = 0; t < 4; t++) acc[mi][ni][t] = 0.f;

    // ---- global load helpers (register staging) ----
    float4 ra0, ra1;           // A staging
    float4 rb0, rb1;           // B staging (BTRANS)
    float  rbs[8];             // B staging (k-major)

    auto loadA = [&](int k0) {
        ra0 = make_float4(0.f, 0.f, 0.f, 0.f);
        ra1 = make_float4(0.f, 0.f, 0.f, 0.f);
        const int kg = k0 + lkq;
        if (AMODE == 2) {
            if (kg < 128) {
                if (v0) { ra0 = *(const float4*)(A + (long)g0 * 128 + kg);
                          ra0.x *= s0; ra0.y *= s0; ra0.z *= s0; ra0.w *= s0; }
                if (v1) { ra1 = *(const float4*)(A + (long)g1 * 128 + kg);
                          ra1.x *= s1; ra1.y *= s1; ra1.z *= s1; ra1.w *= s1; }
            } else {
                if (v0) ra0 = *(const float4*)(A2 + (long)g0 * 128 + (kg - 128));
                if (v1) ra1 = *(const float4*)(A2 + (long)g1 * 128 + (kg - 128));
            }
        } else {
            if (v0) ra0 = *(const float4*)(A + ar0 * lda + kg);
            if (v1) ra1 = *(const float4*)(A + ar1 * lda + kg);
        }
    };
    auto loadB = [&](int k0) {
        if (BTRANS) {
            rb0 = *(const float4*)(B + (long)(colBase + lr0) * ldb + boff + k0 + lkq);
            rb1 = *(const float4*)(B + (long)(colBase + lr1) * ldb + boff + k0 + lkq);
        } else {
#pragma unroll
            for (int i = 0; i < 8; i++) {
                const int slot = tid + i * 256;      // 0..2047
                const int k = slot >> 7;             // 0..15
                const int n = slot & 127;            // 0..127
                rbs[i] = B[(long)(k0 + k) * ldb + colBase + n];
            }
        }
    };
    auto stsTile = [&](int st) {
        float4 t;
        t.x = tf32f(ra0.x); t.y = tf32f(ra0.y); t.z = tf32f(ra0.z); t.w = tf32f(ra0.w);
        *(float4*)&As[st][lr0][lkq] = t;
        t.x = tf32f(ra1.x); t.y = tf32f(ra1.y); t.z = tf32f(ra1.z); t.w = tf32f(ra1.w);
        *(float4*)&As[st][lr1][lkq] = t;
        if (BTRANS) {
            t.x = tf32f(rb0.x); t.y = tf32f(rb0.y); t.z = tf32f(rb0.z); t.w = tf32f(rb0.w);
            *(float4*)&Bs[st][lr0][lkq] = t;
            t.x = tf32f(rb1.x); t.y = tf32f(rb1.y); t.z = tf32f(rb1.z); t.w = tf32f(rb1.w);
            *(float4*)&Bs[st][lr1][lkq] = t;
        } else {
#pragma unroll
            for (int i = 0; i < 8; i++) {
                const int slot = tid + i * 256;
                const int k = slot >> 7;
                const int n = slot & 127;
                Bs[st][n][k] = tf32f(rbs[i]);
            }
        }
    };

    // ---- prologue ----
    loadA(0); loadB(0);
    stsTile(0);
    __syncthreads();

    const int niter = K / GBK;
    int st = 0;
    for (int it = 0; it < niter; ++it) {
        const bool have_next = (it + 1) < niter;
        if (have_next) { loadA((it + 1) * GBK); loadB((it + 1) * GBK); }

        // ---- compute current stage: 2 k8 steps ----
#pragma unroll
        for (int kt = 0; kt < GBK; kt += 8) {
            unsigned a[4][4], b[4][2];
#pragma unroll
            for (int mi = 0; mi < 4; mi++) {
                const int rb = warpM * 64 + mi * 16;
                a[mi][0] = __float_as_uint(As[st][rb + qr    ][kt + qc    ]);
                a[mi][1] = __float_as_uint(As[st][rb + qr + 8][kt + qc    ]);
                a[mi][2] = __float_as_uint(As[st][rb + qr    ][kt + qc + 4]);
                a[mi][3] = __float_as_uint(As[st][rb + qr + 8][kt + qc + 4]);
            }
#pragma unroll
            for (int ni = 0; ni < 4; ni++) {
                const int nb = warpN * 32 + ni * 8;
                b[ni][0] = __float_as_uint(Bs[st][nb + qr][kt + qc    ]);
                b[ni][1] = __float_as_uint(Bs[st][nb + qr][kt + qc + 4]);
            }
#pragma unroll
            for (int mi = 0; mi < 4; mi++)
#pragma unroll
                for (int ni = 0; ni < 4; ni++)
                    asm volatile(
                        "mma.sync.aligned.m16n8k8.row.col.f32.tf32.tf32.f32 "
                        "{%0,%1,%2,%3}, {%4,%5,%6,%7}, {%8,%9}, {%0,%1,%2,%3};\n"
                        : "+f"(acc[mi][ni][0]), "+f"(acc[mi][ni][1]),
                          "+f"(acc[mi][ni][2]), "+f"(acc[mi][ni][3])
                        : "r"(a[mi][0]), "r"(a[mi][1]), "r"(a[mi][2]), "r"(a[mi][3]),
                          "r"(b[ni][0]), "r"(b[ni][1]));
        }

        if (have_next) {
            stsTile(st ^ 1);
            __syncthreads();
        }
        st ^= 1;
    }

    // ---- epilogue ----
#pragma unroll
    for (int mi = 0; mi < 4; mi++) {
        const int row0 = rowBase + warpM * 64 + mi * 16 + qr;
        const int row8 = row0 + 8;
#pragma unroll
        for (int ni = 0; ni < 4; ni++) {
            const int col = colBase + warpN * 32 + ni * 8 + 2 * qc;
            if (row0 < M)
                *(float2*)(C + (long)row0 * ldc + col) =
                    make_float2(acc[mi][ni][0], acc[mi][ni][1]);
            if (row8 < M)
                *(float2*)(C + (long)row8 * ldc + col) =
                    make_float2(acc[mi][ni][2], acc[mi][ni][3]);
        }
    }
}

// ---------------------------------------------------------------------------
// Zero a float buffer
// ---------------------------------------------------------------------------
__global__ void zero_kernel(float4* __restrict__ p, long n4)
{
    long i = (long)blockIdx.x * blockDim.x + threadIdx.x;
    if (i < n4) p[i] = make_float4(0.f, 0.f, 0.f, 0.f);
}

// ---------------------------------------------------------------------------
// Edge scatter: agg[dst] += hW[src]. 1 edge/warp, red.global.add.v4.f32/lane.
// ---------------------------------------------------------------------------
__global__ __launch_bounds__(256)
void scatter_kernel(const float* __restrict__ hW,
                    const int* __restrict__ esrc,
                    const int* __restrict__ edst,
                    float* __restrict__ agg, int E)
{
    const int warpId = (int)(((long)blockIdx.x * blockDim.x + threadIdx.x) >> 5);
    const int lane = threadIdx.x & 31;
    if (warpId >= E) return;
    const int s = esrc[warpId];
    const int d = edst[warpId];
    float4 v = *(const float4*)(hW + (long)s * 128 + lane * 4);
    float* dst = agg + (long)d * 128 + lane * 4;
    asm volatile("red.global.add.v4.f32 [%0], {%1, %2, %3, %4};"
                 :: "l"(dst), "f"(v.x), "f"(v.y), "f"(v.z), "f"(v.w)
                 : "memory");
}

// ---------------------------------------------------------------------------
// GRU elementwise + relu + row L2-normalize. One 128-thr block per node.
// ---------------------------------------------------------------------------
__global__ __launch_bounds__(128)
void gru_kernel(const float* __restrict__ gx, const float* __restrict__ gh,
                const float* __restrict__ bih, const float* __restrict__ bhh,
                const float* __restrict__ erb, float* __restrict__ out, int Nn)
{
    const int n = blockIdx.x;
    const int j = threadIdx.x;
    if (n >= Nn) return;
    const float* gxr = gx + (long)n * 384;
    const float* ghr = gh + (long)n * 384;

    float xr = gxr[j]       + bih[j];
    float xz = gxr[128 + j] + bih[128 + j];
    float xn = gxr[256 + j] + bih[256 + j];
    float hr = ghr[j]       + bhh[j];
    float hz = ghr[128 + j] + bhh[128 + j];
    float hn = ghr[256 + j] + bhh[256 + j];

    float r  = 1.f / (1.f + expf(-(xr + hr)));
    float z  = 1.f / (1.f + expf(-(xz + hz)));
    float nn = tanhf(xn + r * hn);
    float h  = erb[(long)n * 128 + j];
    float o  = (1.f - z) * nn + z * h;
    o = fmaxf(o, 0.f);

    float ss = o * o;
#pragma unroll
    for (int off = 16; off; off >>= 1)
        ss += __shfl_xor_sync(0xffffffffu, ss, off);
    __shared__ float ws[4];
    if ((j & 31) == 0) ws[j >> 5] = ss;
    __syncthreads();
    float total = ws[0] + ws[1] + ws[2] + ws[3];
    float norm = fmaxf(sqrtf(total), 1e-12f);
    out[(long)n * 128 + j] = o / norm;
}

// ---------------------------------------------------------------------------
// kernel_launch
// Inputs: 0 ent_embs, 1 rel_embs, 2 e_r_bias, 3 out_norm, 4 weight_neighbor,
// 5 gru_w_ih, 6 gru_w_hh, 7 gru_b_ih, 8 gru_b_hh, 9 node_id(i32),
// 10 edge_src(i32), 11 edge_dst(i32), 12 g_idx
// ---------------------------------------------------------------------------
extern "C" void kernel_launch(void* const* d_in, const int* in_sizes, int n_in,
                              void* d_out, int out_size)
{
    const float* ent_embs = (const float*)d_in[0];
    const float* e_r_bias = (const float*)d_in[2];
    const float* out_norm = (const float*)d_in[3];
    const float* w_nb     = (const float*)d_in[4];
    const float* w_ih     = (const float*)d_in[5];
    const float* w_hh     = (const float*)d_in[6];
    const float* b_ih     = (const float*)d_in[7];
    const float* b_hh     = (const float*)d_in[8];
    const int*   node_id  = (const int*)d_in[9];
    const int*   edge_src = (const int*)d_in[10];
    const int*   edge_dst = (const int*)d_in[11];

    const int Nn = in_sizes[3];
    const int E  = in_sizes[10];

    float* hW;  cudaGetSymbolAddress((void**)&hW,  g_hW);
    float* agg; cudaGetSymbolAddress((void**)&agg, g_agg);
    float* gx;  cudaGetSymbolAddress((void**)&gx,  g_gx);
    float* gh;  cudaGetSymbolAddress((void**)&gh,  g_gh);

    float* out = (float*)d_out;
    const int Mb = (Nn + GBM - 1) / GBM;

    // 1) hW = ent_embs[node_id] @ W   (B k-major [128,128])
    {
        dim3 grid(128 / GBN, Mb);
        tf32_gemm2<1, false><<<grid, 256>>>(Nn, 128, 128,
                                            ent_embs, 128, nullptr, nullptr, node_id,
                                            w_nb, 128, 0, hW, 128);
    }

    // 2) zero agg
    {
        long n4 = (long)Nn * 128 / 4;
        zero_kernel<<<(int)((n4 + 255) / 256), 256>>>((float4*)agg, n4);
    }

    // 3) scatter: agg[dst] += hW[src]
    {
        long threads = (long)E * 32;
        scatter_kernel<<<(int)((threads + 255) / 256), 256>>>(hW, edge_src, edge_dst, agg, E);
    }

    // 4) gx = [agg*out_norm | e_r_bias] @ w_ih^T   (fused concat, B row-major [384,256])
    {
        dim3 grid(384 / GBN, Mb);
        tf32_gemm2<2, true><<<grid, 256>>>(Nn, 384, 256,
                                           agg, 128, e_r_bias, out_norm, nullptr,
                                           w_ih, 256, 0, gx, 384);
    }

    // 5) gh = e_r_bias @ w_hh^T   (B row-major [384,128])
    {
        dim3 grid(384 / GBN, Mb);
        tf32_gemm2<0, true><<<grid, 256>>>(Nn, 384, 128,
                                           e_r_bias, 128, nullptr, nullptr, nullptr,
                                           w_hh, 128, 0, gh, 384);
    }

    // 6) GRU + relu + normalize
    gru_kernel<<<Nn, 128>>>(gx, gh, b_ih, b_hh, e_r_bias, out, Nn);

    (void)n_in; (void)out_size;
}

// round 5
// speedup vs baseline: 2.0484x; 1.0530x over previous
#include <cuda_runtime.h>
#include <cuda_bf16.h>

// ---------------------------------------------------------------------------
// Problem constants
// ---------------------------------------------------------------------------
#define MAX_NODES 100000
#define MAX_EDGES 1600000

// Scratch (device globals; allocations forbidden)
__device__ float g_hW  [(size_t)MAX_NODES * 128];   // 51.2 MB
__device__ float g_agg [(size_t)MAX_NODES * 128];   // 51.2 MB
__device__ float g_gx  [(size_t)MAX_NODES * 384];   // 153.6 MB
__device__ float g_gh  [(size_t)MAX_NODES * 384];   // 153.6 MB

__device__ __forceinline__ unsigned f2tf32(float x) {
    unsigned r;
    asm("cvt.rna.tf32.f32 %0, %1;" : "=r"(r) : "f"(x));
    return r;
}
__device__ __forceinline__ float tf32f(float x) { return __uint_as_float(f2tf32(x)); }

__device__ __forceinline__ void ldsm_x4(unsigned& r0, unsigned& r1,
                                        unsigned& r2, unsigned& r3, unsigned addr) {
    asm volatile("ldmatrix.sync.aligned.m8n8.x4.shared.b16 {%0,%1,%2,%3}, [%4];"
                 : "=r"(r0), "=r"(r1), "=r"(r2), "=r"(r3) : "r"(addr));
}

// Swizzled offset (in floats) of 16B quad q of row `row` inside a [rows][16]
// float tile. Conflict-free for ldmatrix 8-row phases and bijective per row.
__device__ __forceinline__ int swz_off(int row, int q) {
    return row * 16 + (((q) ^ (row & 3) ^ ((row >> 2) & 1)) << 2);
}

// ---------------------------------------------------------------------------
// TF32 tensor-core GEMM v3 (ldmatrix fragments, XOR-swizzled smem).
//   C[M,N] = Aeff[M,K] @ Beff[K,N]
//   Beff[k][n] = BTRANS ? B[n*ldb + k] : B[k*ldb + n]
//   AMODE 0: Aeff = A (lda)
//   AMODE 1: Aeff row r = A[gidx[r]] (lda)
//   AMODE 2: Aeff row r = [A[r]*rowscale[r] (128) | A2[r] (128)], K == 256
// Block: 256 thr (8 warps, 2M x 4N), tile 128x128, warp tile 64x32, BK=16.
// Double-buffered smem, register-staged global prefetch.
// ---------------------------------------------------------------------------
#define GBM 128
#define GBN 128
#define GBK 16

template<int AMODE, bool BTRANS>
__global__ __launch_bounds__(256, 2)
void tf32_gemm3(int M, int N, int K,
                const float* __restrict__ A, int lda,
                const float* __restrict__ A2,
                const float* __restrict__ rowscale,
                const int* __restrict__ gidx,
                const float* __restrict__ B, int ldb,
                float* __restrict__ C, int ldc)
{
    __shared__ float As[2][GBM * GBK];
    __shared__ float Bs[2][GBN * GBK];

    const int tid  = threadIdx.x;
    const int lane = tid & 31;
    const int warp = tid >> 5;
    const int warpM = warp & 1;    // 2 warps along M (2*64 = 128)
    const int warpN = warp >> 1;   // 4 warps along N (4*32 = 128)
    const int qr = lane >> 2;      // 0..7
    const int qc = lane & 3;       // 0..3

    const int rowBase = blockIdx.y * GBM;
    const int colBase = blockIdx.x * GBN;

    // ldmatrix per-thread geometry
    const int a_fr = (lane & 7) + (((lane >> 3) & 1) << 3);  // row within 16-row m-tile
    const int a_hi = (lane >> 4) & 1;                        // quad +1 for lanes 16-31
    const int b_fr = (lane & 7) + (((lane >> 4) & 1) << 3);  // row within 16-row n-tile
    const int b_hi = (lane >> 3) & 1;                        // quad +1 for lanes 8-15

    // ---- loader mapping: 512 float4 slots per tile, 2 per thread ----
    const int lr0 = tid >> 2;          // rows lr0 and lr0+64
    const int lr1 = lr0 + 64;
    const int lq  = tid & 3;           // k-quad (0..3)

    const int g0 = rowBase + lr0;
    const int g1 = rowBase + lr1;
    const bool v0 = g0 < M;
    const bool v1 = g1 < M;

    long ar0 = 0, ar1 = 0;
    float s0 = 0.f, s1 = 0.f;
    if (AMODE == 1) {
        ar0 = v0 ? (long)gidx[g0] : 0;
        ar1 = v1 ? (long)gidx[g1] : 0;
    } else {
        ar0 = g0; ar1 = g1;
    }
    if (AMODE == 2) {
        s0 = v0 ? rowscale[g0] : 0.f;
        s1 = v1 ? rowscale[g1] : 0.f;
    }

    float acc[4][4][4];
#pragma unroll
    for (int mi = 0; mi < 4; mi++)
#pragma unroll
        for (int ni = 0; ni < 4; ni++)
#pragma unroll
            for (int t = 0; t < 4; t++) acc[mi][ni][t] = 0.f;

    // ---- global load staging ----
    float4 ra0, ra1;
    float4 rb0, rb1;
    float  rbs[8];

    auto loadA = [&](int k0) {
        ra0 = make_float4(0.f, 0.f, 0.f, 0.f);
        ra1 = make_float4(0.f, 0.f, 0.f, 0.f);
        const int kg = k0 + lq * 4;
        if (AMODE == 2) {
            if (kg < 128) {
                if (v0) { ra0 = *(const float4*)(A + (long)g0 * 128 + kg);
                          ra0.x *= s0; ra0.y *= s0; ra0.z *= s0; ra0.w *= s0; }
                if (v1) { ra1 = *(const float4*)(A + (long)g1 * 128 + kg);
                          ra1.x *= s1; ra1.y *= s1; ra1.z *= s1; ra1.w *= s1; }
            } else {
                if (v0) ra0 = *(const float4*)(A2 + (long)g0 * 128 + (kg - 128));
                if (v1) ra1 = *(const float4*)(A2 + (long)g1 * 128 + (kg - 128));
            }
        } else {
            if (v0) ra0 = *(const float4*)(A + ar0 * lda + kg);
            if (v1) ra1 = *(const float4*)(A + ar1 * lda + kg);
        }
    };
    auto loadB = [&](int k0) {
        if (BTRANS) {
            rb0 = *(const float4*)(B + (long)(colBase + lr0) * ldb + k0 + lq * 4);
            rb1 = *(const float4*)(B + (long)(colBase + lr1) * ldb + k0 + lq * 4);
        } else {
#pragma unroll
            for (int i = 0; i < 8; i++) {
                const int slot = tid + i * 256;      // 0..2047
                const int k = slot >> 7;             // 0..15
                const int n = slot & 127;            // 0..127
                rbs[i] = B[(long)(k0 + k) * ldb + colBase + n];
            }
        }
    };
    auto stsTile = [&](int st) {
        float4 t;
        t.x = tf32f(ra0.x); t.y = tf32f(ra0.y); t.z = tf32f(ra0.z); t.w = tf32f(ra0.w);
        *(float4*)&As[st][swz_off(lr0, lq)] = t;
        t.x = tf32f(ra1.x); t.y = tf32f(ra1.y); t.z = tf32f(ra1.z); t.w = tf32f(ra1.w);
        *(float4*)&As[st][swz_off(lr1, lq)] = t;
        if (BTRANS) {
            t.x = tf32f(rb0.x); t.y = tf32f(rb0.y); t.z = tf32f(rb0.z); t.w = tf32f(rb0.w);
            *(float4*)&Bs[st][swz_off(lr0, lq)] = t;
            t.x = tf32f(rb1.x); t.y = tf32f(rb1.y); t.z = tf32f(rb1.z); t.w = tf32f(rb1.w);
            *(float4*)&Bs[st][swz_off(lr1, lq)] = t;
        } else {
#pragma unroll
            for (int i = 0; i < 8; i++) {
                const int slot = tid + i * 256;
                const int k = slot >> 7;
                const int n = slot & 127;
                Bs[st][swz_off(n, k >> 2) + (k & 3)] = tf32f(rbs[i]);
            }
        }
    };

    // ---- prologue ----
    loadA(0); loadB(0);
    stsTile(0);
    __syncthreads();

    const int niter = K / GBK;
    int st = 0;
    for (int it = 0; it < niter; ++it) {
        const bool have_next = (it + 1) < niter;
        if (have_next) { loadA((it + 1) * GBK); loadB((it + 1) * GBK); }

        const unsigned asA = (unsigned)__cvta_generic_to_shared(&As[st][0]);
        const unsigned asB = (unsigned)__cvta_generic_to_shared(&Bs[st][0]);

#pragma unroll
        for (int kt = 0; kt < GBK; kt += 8) {
            unsigned a[4][4], b[4][2];
            const int qa = (kt >> 2) + a_hi;
            const int qb = (kt >> 2) + b_hi;
#pragma unroll
            for (int mi = 0; mi < 4; mi++) {
                const int row = warpM * 64 + mi * 16 + a_fr;
                ldsm_x4(a[mi][0], a[mi][1], a[mi][2], a[mi][3],
                        asA + (unsigned)(swz_off(row, qa) * 4));
            }
#pragma unroll
            for (int p = 0; p < 2; p++) {
                const int n = warpN * 32 + p * 16 + b_fr;
                ldsm_x4(b[2*p][0], b[2*p][1], b[2*p+1][0], b[2*p+1][1],
                        asB + (unsigned)(swz_off(n, qb) * 4));
            }
#pragma unroll
            for (int mi = 0; mi < 4; mi++)
#pragma unroll
                for (int ni = 0; ni < 4; ni++)
                    asm volatile(
                        "mma.sync.aligned.m16n8k8.row.col.f32.tf32.tf32.f32 "
                        "{%0,%1,%2,%3}, {%4,%5,%6,%7}, {%8,%9}, {%0,%1,%2,%3};\n"
                        : "+f"(acc[mi][ni][0]), "+f"(acc[mi][ni][1]),
                          "+f"(acc[mi][ni][2]), "+f"(acc[mi][ni][3])
                        : "r"(a[mi][0]), "r"(a[mi][1]), "r"(a[mi][2]), "r"(a[mi][3]),
                          "r"(b[ni][0]), "r"(b[ni][1]));
        }

        if (have_next) {
            stsTile(st ^ 1);
            __syncthreads();
        }
        st ^= 1;
    }

    // ---- epilogue ----
#pragma unroll
    for (int mi = 0; mi < 4; mi++) {
        const int row0 = rowBase + warpM * 64 + mi * 16 + qr;
        const int row8 = row0 + 8;
#pragma unroll
        for (int ni = 0; ni < 4; ni++) {
            const int col = colBase + warpN * 32 + ni * 8 + 2 * qc;
            if (row0 < M)
                *(float2*)(C + (long)row0 * ldc + col) =
                    make_float2(acc[mi][ni][0], acc[mi][ni][1]);
            if (row8 < M)
                *(float2*)(C + (long)row8 * ldc + col) =
                    make_float2(acc[mi][ni][2], acc[mi][ni][3]);
        }
    }
}

// ---------------------------------------------------------------------------
// Zero a float buffer
// ---------------------------------------------------------------------------
__global__ void zero_kernel(float4* __restrict__ p, long n4)
{
    long i = (long)blockIdx.x * blockDim.x + threadIdx.x;
    if (i < n4) p[i] = make_float4(0.f, 0.f, 0.f, 0.f);
}

// ---------------------------------------------------------------------------
// Edge scatter: agg[dst] += hW[src]. 1 edge/warp, red.global.add.v4.f32/lane.
// ---------------------------------------------------------------------------
__global__ __launch_bounds__(256)
void scatter_kernel(const float* __restrict__ hW,
                    const int* __restrict__ esrc,
                    const int* __restrict__ edst,
                    float* __restrict__ agg, int E)
{
    const int warpId = (int)(((long)blockIdx.x * blockDim.x + threadIdx.x) >> 5);
    const int lane = threadIdx.x & 31;
    if (warpId >= E) return;
    const int s = esrc[warpId];
    const int d = edst[warpId];
    float4 v = *(const float4*)(hW + (long)s * 128 + lane * 4);
    float* dst = agg + (long)d * 128 + lane * 4;
    asm volatile("red.global.add.v4.f32 [%0], {%1, %2, %3, %4};"
                 :: "l"(dst), "f"(v.x), "f"(v.y), "f"(v.z), "f"(v.w)
                 : "memory");
}

// ---------------------------------------------------------------------------
// GRU elementwise + relu + row L2-normalize. One 128-thr block per node.
// ---------------------------------------------------------------------------
__global__ __launch_bounds__(128)
void gru_kernel(const float* __restrict__ gx, const float* __restrict__ gh,
                const float* __restrict__ bih, const float* __restrict__ bhh,
                const float* __restrict__ erb, float* __restrict__ out, int Nn)
{
    const int n = blockIdx.x;
    const int j = threadIdx.x;
    if (n >= Nn) return;
    const float* gxr = gx + (long)n * 384;
    const float* ghr = gh + (long)n * 384;

    float xr = gxr[j]       + bih[j];
    float xz = gxr[128 + j] + bih[128 + j];
    float xn = gxr[256 + j] + bih[256 + j];
    float hr = ghr[j]       + bhh[j];
    float hz = ghr[128 + j] + bhh[128 + j];
    float hn = ghr[256 + j] + bhh[256 + j];

    float r  = 1.f / (1.f + expf(-(xr + hr)));
    float z  = 1.f / (1.f + expf(-(xz + hz)));
    float nn = tanhf(xn + r * hn);
    float h  = erb[(long)n * 128 + j];
    float o  = (1.f - z) * nn + z * h;
    o = fmaxf(o, 0.f);

    float ss = o * o;
#pragma unroll
    for (int off = 16; off; off >>= 1)
        ss += __shfl_xor_sync(0xffffffffu, ss, off);
    __shared__ float ws[4];
    if ((j & 31) == 0) ws[j >> 5] = ss;
    __syncthreads();
    float total = ws[0] + ws[1] + ws[2] + ws[3];
    float norm = fmaxf(sqrtf(total), 1e-12f);
    out[(long)n * 128 + j] = o / norm;
}

// ---------------------------------------------------------------------------
// kernel_launch
// Inputs: 0 ent_embs, 1 rel_embs, 2 e_r_bias, 3 out_norm, 4 weight_neighbor,
// 5 gru_w_ih, 6 gru_w_hh, 7 gru_b_ih, 8 gru_b_hh, 9 node_id(i32),
// 10 edge_src(i32), 11 edge_dst(i32), 12 g_idx
// ---------------------------------------------------------------------------
extern "C" void kernel_launch(void* const* d_in, const int* in_sizes, int n_in,
                              void* d_out, int out_size)
{
    const float* ent_embs = (const float*)d_in[0];
    const float* e_r_bias = (const float*)d_in[2];
    const float* out_norm = (const float*)d_in[3];
    const float* w_nb     = (const float*)d_in[4];
    const float* w_ih     = (const float*)d_in[5];
    const float* w_hh     = (const float*)d_in[6];
    const float* b_ih     = (const float*)d_in[7];
    const float* b_hh     = (const float*)d_in[8];
    const int*   node_id  = (const int*)d_in[9];
    const int*   edge_src = (const int*)d_in[10];
    const int*   edge_dst = (const int*)d_in[11];

    const int Nn = in_sizes[3];
    const int E  = in_sizes[10];

    float* hW;  cudaGetSymbolAddress((void**)&hW,  g_hW);
    float* agg; cudaGetSymbolAddress((void**)&agg, g_agg);
    float* gx;  cudaGetSymbolAddress((void**)&gx,  g_gx);
    float* gh;  cudaGetSymbolAddress((void**)&gh,  g_gh);

    float* out = (float*)d_out;
    const int Mb = (Nn + GBM - 1) / GBM;

    // 1) hW = ent_embs[node_id] @ W   (B k-major [128,128])
    {
        dim3 grid(128 / GBN, Mb);
        tf32_gemm3<1, false><<<grid, 256>>>(Nn, 128, 128,
                                            ent_embs, 128, nullptr, nullptr, node_id,
                                            w_nb, 128, hW, 128);
    }

    // 2) zero agg
    {
        long n4 = (long)Nn * 128 / 4;
        zero_kernel<<<(int)((n4 + 255) / 256), 256>>>((float4*)agg, n4);
    }

    // 3) scatter: agg[dst] += hW[src]
    {
        long threads = (long)E * 32;
        scatter_kernel<<<(int)((threads + 255) / 256), 256>>>(hW, edge_src, edge_dst, agg, E);
    }

    // 4) gx = [agg*out_norm | e_r_bias] @ w_ih^T   (fused concat, B row-major [384,256])
    {
        dim3 grid(384 / GBN, Mb);
        tf32_gemm3<2, true><<<grid, 256>>>(Nn, 384, 256,
                                           agg, 128, e_r_bias, out_norm, nullptr,
                                           w_ih, 256, gx, 384);
    }

    // 5) gh = e_r_bias @ w_hh^T   (B row-major [384,128])
    {
        dim3 grid(384 / GBN, Mb);
        tf32_gemm3<0, true><<<grid, 256>>>(Nn, 384, 128,
                                           e_r_bias, 128, nullptr, nullptr, nullptr,
                                           w_hh, 128, gh, 384);
    }

    // 6) GRU + relu + normalize
    gru_kernel<<<Nn, 128>>>(gx, gh, b_ih, b_hh, e_r_bias, out, Nn);

    (void)n_in; (void)out_size;
}